// round 16
// baseline (speedup 1.0000x reference)
#include <cuda_runtime.h>
#include <cfloat>
#include <math.h>

#define B_ 32
#define T_ 2048
#define O_ 128
#define C_ 80
#define NTH 256
#define TPT (T_ / NTH)          // 8 tokens per thread
#define EPSF 1e-7f

extern "C" __device__ float __nv_expf(float);
extern "C" __device__ float __nv_logf(float);

// ---------------------------------------------------------------------------
// Fused JV-LSA with on-the-fly cost:
//   cost(t,o) = (1 - GIoU(pred_t, tgt_o)) + (lsum_t - (logit[t][cls_o] - mx_t))
// f32 ops pinned __f*_rn (no FMA), libdevice exp/log, XLA-style warp-tree
// exp-sum. fp64 duals, first-index argmin ties (numpy JV replica).
// One block per batch, 256 threads, column j owned by thread j%256.
// OUTPUT IS WRITTEN AS FLOAT32 (harness loads output.bin as np.float32).
// ---------------------------------------------------------------------------
__global__ void __launch_bounds__(NTH, 1) lsa_kernel(
    const float* __restrict__ pred_b,   // [B,T,4]
    const float* __restrict__ tgt_b,    // [B,O,4]
    const float* __restrict__ pred_c,   // [B,T,C]
    const int*   __restrict__ tgt_c,    // [B,O]
    float* __restrict__ out)            // [2,B,O] as float32!
{
    const int b   = blockIdx.x;
    const int tid = threadIdx.x;

    __shared__ double shortest[T_];
    __shared__ double v[T_];
    __shared__ double u[O_];
    __shared__ signed char path[T_];
    __shared__ signed char row4col[T_];
    __shared__ short col4row[O_];
    __shared__ unsigned char SC[T_];
    __shared__ unsigned char SR[O_];
    __shared__ float s_tx1[O_], s_ty1[O_], s_tx2[O_], s_ty2[O_], s_a2[O_];
    __shared__ int   s_cls[O_];
    __shared__ double s_min;
    __shared__ int    s_next, s_sink;
    __shared__ double w_val[NTH / 32];
    __shared__ int    w_idx[NTH / 32];

    float r_x1[TPT], r_y1[TPT], r_x2[TPT], r_y2[TPT], r_a1[TPT];
    float r_mx[TPT], r_ls[TPT];

    if (tid < O_) {
        const float* tb = tgt_b + ((long)b * O_ + tid) * 4;
        const float tx = tb[0], ty = tb[1], tw = tb[2], th = tb[3];
        const float x1 = __fsub_rn(tx, __fmul_rn(tw, 0.5f));
        const float y1 = __fsub_rn(ty, __fmul_rn(th, 0.5f));
        const float x2 = __fadd_rn(tx, __fmul_rn(tw, 0.5f));
        const float y2 = __fadd_rn(ty, __fmul_rn(th, 0.5f));
        s_tx1[tid] = x1; s_ty1[tid] = y1; s_tx2[tid] = x2; s_ty2[tid] = y2;
        const float w2 = __fsub_rn(x2, x1);
        const float h2 = __fadd_rn(__fsub_rn(y2, y1), EPSF);
        s_a2[tid] = __fmul_rn(w2, h2);
        int c = tgt_c[b * O_ + tid];
        s_cls[tid] = (c >= 0 && c < C_) ? c : 0;
    }

    #pragma unroll
    for (int k = 0; k < TPT; ++k) {
        const int t = tid + k * NTH;
        const float* pb = pred_b + ((long)b * T_ + t) * 4;
        const float px = pb[0], py = pb[1], pw = pb[2], ph = pb[3];
        const float x1 = __fsub_rn(px, __fmul_rn(pw, 0.5f));
        const float y1 = __fsub_rn(py, __fmul_rn(ph, 0.5f));
        const float x2 = __fadd_rn(px, __fmul_rn(pw, 0.5f));
        const float y2 = __fadd_rn(py, __fmul_rn(ph, 0.5f));
        r_x1[k] = x1; r_y1[k] = y1; r_x2[k] = x2; r_y2[k] = y2;
        const float w1 = __fsub_rn(x2, x1);
        const float h1 = __fadd_rn(__fsub_rn(y2, y1), EPSF);
        r_a1[k] = __fmul_rn(w1, h1);

        const float* lg = pred_c + ((long)b * T_ + t) * C_;
        float mx = -FLT_MAX;
        for (int c = 0; c < C_; ++c) mx = fmaxf(mx, lg[c]);
        float s[32];
        #pragma unroll
        for (int l = 0; l < 32; ++l) {
            float a = __nv_expf(__fsub_rn(lg[l], mx));
            a = __fadd_rn(a, __nv_expf(__fsub_rn(lg[l + 32], mx)));
            if (l < 16) a = __fadd_rn(a, __nv_expf(__fsub_rn(lg[l + 64], mx)));
            s[l] = a;
        }
        #pragma unroll
        for (int off = 16; off > 0; off >>= 1)
            for (int l = 0; l + off < 32; ++l)
                s[l] = __fadd_rn(s[l], s[l + off]);
        r_mx[k] = mx;
        r_ls[k] = __nv_logf(s[0]);
    }

    #pragma unroll
    for (int k = 0; k < TPT; ++k) { const int j = tid + k * NTH; v[j] = 0.0; row4col[j] = -1; }
    if (tid < O_) { u[tid] = 0.0; col4row[tid] = -1; }
    __syncthreads();

    for (int cur = 0; cur < O_; ++cur) {
        #pragma unroll
        for (int k = 0; k < TPT; ++k) { const int j = tid + k * NTH; shortest[j] = DBL_MAX; SC[j] = 0; path[j] = 0; }
        if (tid < O_) SR[tid] = 0;
        if (tid == 0) { s_min = 0.0; s_next = cur; s_sink = -1; }
        __syncthreads();

        for (int step = 0; step < T_; ++step) {
            const int    i    = s_next;
            const double minv = s_min;
            if (tid == 0) SR[i] = 1;
            const double ui = u[i];

            const float b2x1 = s_tx1[i], b2y1 = s_ty1[i];
            const float b2x2 = s_tx2[i], b2y2 = s_ty2[i];
            const float a2   = s_a2[i];
            const float* lcol = pred_c + (long)b * T_ * C_ + s_cls[i];

            double bv = DBL_MAX; int bj = T_ - 1;
            #pragma unroll
            for (int k = 0; k < TPT; ++k) {
                const int j = tid + k * NTH;
                double sj = shortest[j];
                if (!SC[j]) {
                    const float iw = fmaxf(__fsub_rn(fminf(r_x2[k], b2x2), fmaxf(r_x1[k], b2x1)), 0.f);
                    const float ih = fmaxf(__fsub_rn(fminf(r_y2[k], b2y2), fmaxf(r_y1[k], b2y1)), 0.f);
                    const float inter = __fmul_rn(iw, ih);
                    const float uni   = __fadd_rn(__fsub_rn(__fadd_rn(r_a1[k], a2), inter), EPSF);
                    const float iou   = __fdiv_rn(inter, uni);
                    const float cw = __fsub_rn(fmaxf(r_x2[k], b2x2), fminf(r_x1[k], b2x1));
                    const float ch = __fsub_rn(fmaxf(r_y2[k], b2y2), fminf(r_y1[k], b2y1));
                    const float carea = __fadd_rn(__fmul_rn(cw, ch), EPSF);
                    const float giou  = __fsub_rn(iou, __fdiv_rn(__fsub_rn(carea, uni), carea));
                    const float xc    = lcol[(long)j * C_];
                    const float nll   = __fsub_rn(r_ls[k], __fsub_rn(xc, r_mx[k]));
                    const float cf    = __fadd_rn(__fsub_rn(1.0f, giou), nll);
                    const double r = ((minv + (double)cf) - ui) - v[j];
                    if (r < sj) { sj = r; shortest[j] = r; path[j] = (signed char)i; }
                    if (sj < bv) { bv = sj; bj = j; }
                }
            }
            #pragma unroll
            for (int off = 16; off; off >>= 1) {
                const double ov = __shfl_down_sync(0xffffffffu, bv, off);
                const int    oj = __shfl_down_sync(0xffffffffu, bj, off);
                if (ov < bv || (ov == bv && oj < bj)) { bv = ov; bj = oj; }
            }
            if ((tid & 31) == 0) { w_val[tid >> 5] = bv; w_idx[tid >> 5] = bj; }
            __syncthreads();
            if (tid == 0) {
                #pragma unroll
                for (int w = 1; w < NTH / 32; ++w) {
                    if (w_val[w] < bv || (w_val[w] == bv && w_idx[w] < bj)) { bv = w_val[w]; bj = w_idx[w]; }
                }
                s_min = bv;
                SC[bj] = 1;
                const int r4 = (int)row4col[bj];
                if (r4 < 0) s_sink = bj; else s_next = r4;
            }
            __syncthreads();
            if (s_sink >= 0) break;
        }

        const double mv   = s_min;
        const int    sink = s_sink;
        if (tid < O_) {
            if (tid == cur)   u[tid] += mv;
            else if (SR[tid]) {
                int cj = (int)col4row[tid];
                cj = (cj >= 0 && cj < T_) ? cj : 0;
                u[tid] += mv - shortest[cj];
            }
        }
        #pragma unroll
        for (int k = 0; k < TPT; ++k) {
            const int j = tid + k * NTH;
            if (SC[j]) v[j] -= mv - shortest[j];
        }
        __syncthreads();

        if (tid == 0 && sink >= 0) {
            int j = sink;
            for (int s2 = 0; s2 <= O_; ++s2) {
                const int i = (int)path[j];
                row4col[j] = (signed char)i;
                const int tmp = (int)col4row[i];
                col4row[i] = (short)j;
                j = tmp;
                if (i == cur || j < 0 || j >= T_) break;
            }
        }
        __syncthreads();
    }

    // pred_idx = sorted col4row values; tgt_idx = argsort permutation.
    // *** WRITTEN AS FLOAT32 *** — the harness reads output.bin as np.float32.
    if (tid < O_) {
        const int myc = (int)col4row[tid];
        int rank = 0;
        for (int i2 = 0; i2 < O_; ++i2) rank += ((int)col4row[i2] < myc);
        out[b * O_ + rank]           = (float)myc;   // pred_idx
        out[B_ * O_ + b * O_ + rank] = (float)tid;   // tgt_idx
    }
}

// ---------------------------------------------------------------------------
extern "C" void kernel_launch(void* const* d_in, const int* in_sizes, int n_in,
                              void* d_out, int out_size)
{
    const float* pred_b = (const float*)d_in[0];   // [B,T,4]
    const float* tgt_b  = (const float*)d_in[1];   // [B,O,4]
    const float* pred_c = (const float*)d_in[2];   // [B,T,C]
    const int*   tgt_c  = (const int*)d_in[3];     // [B,O]
    float* out = (float*)d_out;                    // float32 output buffer!

    lsa_kernel<<<B_, NTH>>>(pred_b, tgt_b, pred_c, tgt_c, out);
}

// round 17
// speedup vs baseline: 1.1362x; 1.1362x over previous
#include <cuda_runtime.h>
#include <cfloat>
#include <math.h>

#define B_ 32
#define T_ 2048
#define O_ 128
#define C_ 80
#define NTH 256
#define TPT (T_ / NTH)          // 8 columns per thread
#define NW  (NTH / 32)          // 8 warps
#define EPSF 1e-7f

extern "C" __device__ float __nv_expf(float);
extern "C" __device__ float __nv_logf(float);

// Precomputed cost matrix [b][o][t], fp32, 33.5 MB (L2-resident).
__device__ float g_cost[(size_t)B_ * O_ * T_];

// ---------------------------------------------------------------------------
// Cost kernel: full-chip parallel, bit-identical to the passing R16 formulas.
// Block = 128 threads (one token each), grid = (T/128, B).
// ---------------------------------------------------------------------------
__global__ void __launch_bounds__(128) cost_kernel(
    const float* __restrict__ pred_b,   // [B,T,4]
    const float* __restrict__ tgt_b,    // [B,O,4]
    const float* __restrict__ pred_c,   // [B,T,C]
    const int*   __restrict__ tgt_c)    // [B,O]
{
    const int b   = blockIdx.y;
    const int tid = threadIdx.x;
    const int t   = blockIdx.x * 128 + tid;

    __shared__ float s_tx1[O_], s_ty1[O_], s_tx2[O_], s_ty2[O_], s_a2[O_];
    __shared__ int   s_cls[O_];

    if (tid < O_) {
        const float* tb = tgt_b + ((long)b * O_ + tid) * 4;
        const float tx = tb[0], ty = tb[1], tw = tb[2], th = tb[3];
        const float x1 = __fsub_rn(tx, __fmul_rn(tw, 0.5f));
        const float y1 = __fsub_rn(ty, __fmul_rn(th, 0.5f));
        const float x2 = __fadd_rn(tx, __fmul_rn(tw, 0.5f));
        const float y2 = __fadd_rn(ty, __fmul_rn(th, 0.5f));
        s_tx1[tid] = x1; s_ty1[tid] = y1; s_tx2[tid] = x2; s_ty2[tid] = y2;
        const float w2 = __fsub_rn(x2, x1);
        const float h2 = __fadd_rn(__fsub_rn(y2, y1), EPSF);
        s_a2[tid] = __fmul_rn(w2, h2);
        int c = tgt_c[b * O_ + tid];
        s_cls[tid] = (c >= 0 && c < C_) ? c : 0;
    }
    __syncthreads();

    // pred box for this token
    const float* pb = pred_b + ((long)b * T_ + t) * 4;
    const float px = pb[0], py = pb[1], pw = pb[2], ph = pb[3];
    const float x1 = __fsub_rn(px, __fmul_rn(pw, 0.5f));
    const float y1 = __fsub_rn(py, __fmul_rn(ph, 0.5f));
    const float x2 = __fadd_rn(px, __fmul_rn(pw, 0.5f));
    const float y2 = __fadd_rn(py, __fmul_rn(ph, 0.5f));
    const float w1 = __fsub_rn(x2, x1);
    const float h1 = __fadd_rn(__fsub_rn(y2, y1), EPSF);
    const float a1 = __fmul_rn(w1, h1);

    // log-sum-exp, identical bits to R16 (exact max + lane-tree in registers)
    const float* lg = pred_c + ((long)b * T_ + t) * C_;
    float mx = -FLT_MAX;
    for (int c = 0; c < C_; ++c) mx = fmaxf(mx, lg[c]);
    float s[32];
    #pragma unroll
    for (int l = 0; l < 32; ++l) {
        float a = __nv_expf(__fsub_rn(lg[l], mx));
        a = __fadd_rn(a, __nv_expf(__fsub_rn(lg[l + 32], mx)));
        if (l < 16) a = __fadd_rn(a, __nv_expf(__fsub_rn(lg[l + 64], mx)));
        s[l] = a;
    }
    #pragma unroll
    for (int off = 16; off > 0; off >>= 1)
        for (int l = 0; l + off < 32; ++l)
            s[l] = __fadd_rn(s[l], s[l + off]);
    const float ls = __nv_logf(s[0]);

    float* cb = g_cost + (long)b * O_ * T_ + t;
    #pragma unroll 4
    for (int o = 0; o < O_; ++o) {
        const float b2x1 = s_tx1[o], b2y1 = s_ty1[o];
        const float b2x2 = s_tx2[o], b2y2 = s_ty2[o];
        const float iw = fmaxf(__fsub_rn(fminf(x2, b2x2), fmaxf(x1, b2x1)), 0.f);
        const float ih = fmaxf(__fsub_rn(fminf(y2, b2y2), fmaxf(y1, b2y1)), 0.f);
        const float inter = __fmul_rn(iw, ih);
        const float uni   = __fadd_rn(__fsub_rn(__fadd_rn(a1, s_a2[o]), inter), EPSF);
        const float iou   = __fdiv_rn(inter, uni);
        const float cw = __fsub_rn(fmaxf(x2, b2x2), fminf(x1, b2x1));
        const float ch = __fsub_rn(fmaxf(y2, b2y2), fminf(y1, b2y1));
        const float carea = __fadd_rn(__fmul_rn(cw, ch), EPSF);
        const float giou  = __fsub_rn(iou, __fdiv_rn(__fsub_rn(carea, uni), carea));
        const float xc    = lg[s_cls[o]];
        const float nll   = __fsub_rn(ls, __fsub_rn(xc, mx));
        cb[(long)o * T_] = __fadd_rn(__fsub_rn(1.0f, giou), nll);
    }
}

// ---------------------------------------------------------------------------
// JV-LSA on the precomputed cost matrix. One block/batch, 256 threads.
// One __syncthreads per Dijkstra step (double-buffered warp-argmin slots,
// redundant block reduce, thread-local SC mask and v duals). fp64 duals,
// first-index argmin ties — exact numpy-reference semantics.
// ---------------------------------------------------------------------------
__global__ void __launch_bounds__(NTH, 1) lsa_kernel(float* __restrict__ out)
{
    const int b   = blockIdx.x;
    const int tid = threadIdx.x;
    const float* cbase = g_cost + (long)b * O_ * T_;

    __shared__ double shortest[T_];          // 16 KB (cross-read at dual update)
    __shared__ double u[O_];                 // 1 KB
    __shared__ signed char path[T_];         // 2 KB
    __shared__ signed char row4col[T_];      // 2 KB
    __shared__ short col4row[O_];            // 256 B
    __shared__ unsigned char SR[O_];         // 128 B
    __shared__ double wv[2][NW];
    __shared__ int    wi[2][NW];

    double vloc[TPT];                        // v duals: thread-private forever
    #pragma unroll
    for (int k = 0; k < TPT; ++k) vloc[k] = 0.0;
    #pragma unroll
    for (int k = 0; k < TPT; ++k) row4col[tid + k * NTH] = -1;
    if (tid < O_) { u[tid] = 0.0; col4row[tid] = -1; SR[tid] = 0; }
    __syncthreads();

    for (int cur = 0; cur < O_; ++cur) {
        double sj[TPT];
        unsigned taken = 0;                  // SC for my 8 columns
        #pragma unroll
        for (int k = 0; k < TPT; ++k) sj[k] = DBL_MAX;

        int    i      = cur;
        double minv   = 0.0;
        int    sink   = -1;
        int    parity = 0;
        double mv     = 0.0;

        for (;;) {
            if (tid == 0) SR[i] = 1;
            const double ui = u[i];
            const float* crow = cbase + (long)i * T_;

            // fused relax + local argmin over owned free columns
            double bv = DBL_MAX; int bj = T_;
            #pragma unroll
            for (int k = 0; k < TPT; ++k) {
                if (!((taken >> k) & 1u)) {
                    const int j = tid + k * NTH;
                    const double r = ((minv + (double)crow[j]) - ui) - vloc[k];
                    if (r < sj[k]) { sj[k] = r; shortest[j] = r; path[j] = (signed char)i; }
                    if (sj[k] < bv) { bv = sj[k]; bj = j; }
                }
            }
            // warp argmin (first-index ties)
            #pragma unroll
            for (int off = 16; off; off >>= 1) {
                const double ov = __shfl_down_sync(0xffffffffu, bv, off);
                const int    oj = __shfl_down_sync(0xffffffffu, bj, off);
                if (ov < bv || (ov == bv && oj < bj)) { bv = ov; bj = oj; }
            }
            if ((tid & 31) == 0) { wv[parity][tid >> 5] = bv; wi[parity][tid >> 5] = bj; }
            __syncthreads();                 // the ONE barrier per step

            // every thread reduces the 8 warp slots identically
            bv = wv[parity][0]; bj = wi[parity][0];
            #pragma unroll
            for (int w = 1; w < NW; ++w) {
                const double ov = wv[parity][w]; const int oj = wi[parity][w];
                if (ov < bv || (ov == bv && oj < bj)) { bv = ov; bj = oj; }
            }
            minv = bv;
            if ((bj & (NTH - 1)) == tid) taken |= 1u << (bj >> 8);  // SC[bj]=1, locally
            const int r4 = (int)row4col[bj];
            parity ^= 1;
            if (r4 < 0) { sink = bj; mv = bv; break; }   // uniform decision
            i = r4;
        }

        // dual update (pre-augmentation col4row, exactly like the reference)
        if (tid < O_) {
            if (tid == cur) u[tid] += mv;
            else if (SR[tid]) u[tid] += mv - shortest[col4row[tid]];
            SR[tid] = 0;                      // own-element reset, same phase
        }
        #pragma unroll
        for (int k = 0; k < TPT; ++k)
            if ((taken >> k) & 1u) vloc[k] -= mv - sj[k];
        __syncthreads();

        // augment (sequential pointer chase)
        if (tid == 0) {
            int j = sink;
            for (;;) {
                const int ii = (int)path[j];
                row4col[j] = (signed char)ii;
                const int tmp = (int)col4row[ii];
                col4row[ii] = (short)j;
                j = tmp;
                if (ii == cur) break;
            }
        }
        __syncthreads();
    }

    // pred_idx = sorted col4row values; tgt_idx = argsort permutation.
    // Written as FLOAT32 (harness reads output.bin as np.float32).
    if (tid < O_) {
        const int myc = (int)col4row[tid];
        int rank = 0;
        for (int i2 = 0; i2 < O_; ++i2) rank += ((int)col4row[i2] < myc);
        out[b * O_ + rank]           = (float)myc;   // pred_idx
        out[B_ * O_ + b * O_ + rank] = (float)tid;   // tgt_idx
    }
}

// ---------------------------------------------------------------------------
extern "C" void kernel_launch(void* const* d_in, const int* in_sizes, int n_in,
                              void* d_out, int out_size)
{
    const float* pred_b = (const float*)d_in[0];
    const float* tgt_b  = (const float*)d_in[1];
    const float* pred_c = (const float*)d_in[2];
    const int*   tgt_c  = (const int*)d_in[3];
    float* out = (float*)d_out;

    dim3 cgrid(T_ / 128, B_);
    cost_kernel<<<cgrid, 128>>>(pred_b, tgt_b, pred_c, tgt_c);
    lsa_kernel<<<B_, NTH>>>(out);
}